// round 1
// baseline (speedup 1.0000x reference)
#include <cuda_runtime.h>
#include <math.h>

#define BS   16
#define NP   128
#define MNP  2048
#define D    768
#define NH   12
#define HD   64
#define DFF  2048
#define NLAYERS 2
#define TOPK 32
#define NC   751
#define NTOK (BS*NP)    // 2048
#define NMEM (BS*MNP)   // 32768
#define EPS  1e-5f

// ----------------------------------------------------------------------------
// Scratch (static device globals; no runtime allocation)
// ----------------------------------------------------------------------------
__device__ float g_x   [NTOK*(long)D];
__device__ float g_tmp [NTOK*(long)D];
__device__ float g_q   [NTOK*(long)D];
__device__ float g_qk  [NTOK*(long)(2*D)];
__device__ float g_v   [NTOK*(long)D];
__device__ float g_attn[NTOK*(long)D];
__device__ float g_K   [NMEM*(long)D];
__device__ float g_V   [NMEM*(long)D];
__device__ float g_sims[NTOK*(long)MNP];
__device__ int   g_idx [NTOK*TOPK];
__device__ float g_minv[NMEM];
__device__ float g_h1  [NTOK*(long)DFF];
__device__ float g_bnscale[D];
__device__ float g_bnshift[D];

// ----------------------------------------------------------------------------
// GEMM: C[M,N] = op(A)[M,K] @ B[N,K]^T (+bias) (+gelu)
// MODE bit0: A += A2 (elementwise, e.g. +pos)
// MODE bit1: A affine per-k: a*ascale[k]+ashift[k]  (batchnorm-fused cls head)
// MODE bit2: GELU (exact, erf) epilogue
// ----------------------------------------------------------------------------
template<int MODE>
__global__ void __launch_bounds__(256) gemm_kernel(
    const float* __restrict__ A, const float* __restrict__ A2,
    const float* __restrict__ ascale, const float* __restrict__ ashift,
    const float* __restrict__ B, const float* __restrict__ bias,
    float* __restrict__ C, int M, int N, int K,
    long sA, long sB, long sC)
{
    constexpr int BM = 128, BN = 128, BK = 8;
    int bz = blockIdx.z;
    A += bz * sA;
    if (MODE & 1) A2 += bz * sA;
    B += bz * sB;
    C += bz * sC;
    int bm = blockIdx.y * BM, bn = blockIdx.x * BN;

    __shared__ float As[BK][BM + 4];
    __shared__ float Bs[BK][BN + 4];

    int tid = threadIdx.x;
    int tx = tid & 15, ty = tid >> 4;

    float acc[8][8];
#pragma unroll
    for (int i = 0; i < 8; i++)
#pragma unroll
        for (int j = 0; j < 8; j++) acc[i][j] = 0.f;

    for (int k0 = 0; k0 < K; k0 += BK) {
#pragma unroll
        for (int l = 0; l < 4; l++) {
            int lin = tid + l * 256;
            int kk = lin & 7, r = lin >> 3;
            int m = bm + r;
            float v = 0.f;
            if (m < M) {
                long off = (long)m * K + k0 + kk;
                v = A[off];
                if (MODE & 1) v += A2[off];
                if (MODE & 2) v = v * ascale[k0 + kk] + ashift[k0 + kk];
            }
            As[kk][r] = v;
        }
#pragma unroll
        for (int l = 0; l < 4; l++) {
            int lin = tid + l * 256;
            int kk = lin & 7, r = lin >> 3;
            int n = bn + r;
            Bs[kk][r] = (n < N) ? B[(long)n * K + k0 + kk] : 0.f;
        }
        __syncthreads();
#pragma unroll
        for (int k = 0; k < BK; k++) {
            float a[8], b[8];
            *(float4*)&a[0] = *(const float4*)&As[k][ty * 8];
            *(float4*)&a[4] = *(const float4*)&As[k][ty * 8 + 4];
            *(float4*)&b[0] = *(const float4*)&Bs[k][tx * 8];
            *(float4*)&b[4] = *(const float4*)&Bs[k][tx * 8 + 4];
#pragma unroll
            for (int i = 0; i < 8; i++)
#pragma unroll
                for (int j = 0; j < 8; j++)
                    acc[i][j] = fmaf(a[i], b[j], acc[i][j]);
        }
        __syncthreads();
    }
#pragma unroll
    for (int i = 0; i < 8; i++) {
        int m = bm + ty * 8 + i;
        if (m >= M) continue;
#pragma unroll
        for (int j = 0; j < 8; j++) {
            int n = bn + tx * 8 + j;
            if (n >= N) continue;
            float v = acc[i][j];
            if (bias) v += bias[n];
            if (MODE & 4) v = 0.5f * v * (1.f + erff(v * 0.70710678118654752f));
            C[(long)m * N + n] = v;
        }
    }
}

// ----------------------------------------------------------------------------
// LayerNorm over last dim (D=768): out = LN(x (+ add)) * g + b. One block/row.
// Safe for in-place out==x (row values cached in registers before write).
// ----------------------------------------------------------------------------
__global__ void __launch_bounds__(256) ln_kernel(
    const float* __restrict__ x, const float* __restrict__ add,
    const float* __restrict__ g, const float* __restrict__ b,
    float* __restrict__ out)
{
    int row = blockIdx.x, tid = threadIdx.x;
    const float* xr = x + (long)row * D;
    float vals[3];
    float s = 0.f, sq = 0.f;
#pragma unroll
    for (int i = 0; i < 3; i++) {
        int c = tid + i * 256;
        float v = xr[c];
        if (add) v += add[(long)row * D + c];
        vals[i] = v; s += v; sq += v * v;
    }
    __shared__ float rs[256], rq[256];
    rs[tid] = s; rq[tid] = sq;
    __syncthreads();
    for (int o = 128; o > 0; o >>= 1) {
        if (tid < o) { rs[tid] += rs[tid + o]; rq[tid] += rq[tid + o]; }
        __syncthreads();
    }
    float mu = rs[0] * (1.f / D);
    float var = rq[0] * (1.f / D) - mu * mu;
    float rstd = rsqrtf(var + EPS);
    float* orow = out + (long)row * D;
#pragma unroll
    for (int i = 0; i < 3; i++) {
        int c = tid + i * 256;
        orow[c] = (vals[i] - mu) * rstd * g[c] + b[c];
    }
}

// 1/||memory_row||  (for top-k column scaling)
__global__ void __launch_bounds__(256) rownorm_kernel(
    const float* __restrict__ m, float* __restrict__ minv)
{
    int row = blockIdx.x, tid = threadIdx.x;
    float s = 0.f;
#pragma unroll
    for (int i = 0; i < 3; i++) {
        float v = m[(long)row * D + tid + i * 256];
        s += v * v;
    }
    __shared__ float rs[256];
    rs[tid] = s; __syncthreads();
    for (int o = 128; o > 0; o >>= 1) {
        if (tid < o) rs[tid] += rs[tid + o];
        __syncthreads();
    }
    if (tid == 0) minv[row] = rsqrtf(rs[0]);
}

// ----------------------------------------------------------------------------
// Top-32 per query row of 2048 column-scaled sims (iterative block argmax).
// Tie-break to lowest index (matches jax top_k stability).
// ----------------------------------------------------------------------------
__global__ void __launch_bounds__(256) topk_kernel(
    const float* __restrict__ sims, const float* __restrict__ minv,
    int* __restrict__ idx_out)
{
    int row = blockIdx.x;        // b*NP + q
    int b = row / NP;
    int tid = threadIdx.x;
    __shared__ float s[MNP];
    __shared__ float rmax[256];
    __shared__ int   rarg[256];
    for (int i = tid; i < MNP; i += 256)
        s[i] = sims[(long)row * MNP + i] * minv[b * MNP + i];
    __syncthreads();
    for (int t = 0; t < TOPK; t++) {
        float best = -INFINITY; int bi = 0x7fffffff;
        for (int i = tid; i < MNP; i += 256) {
            float v = s[i];
            if (v > best) { best = v; bi = i; }
        }
        rmax[tid] = best; rarg[tid] = bi;
        __syncthreads();
        for (int o = 128; o > 0; o >>= 1) {
            if (tid < o) {
                float ov = rmax[tid + o]; int oi = rarg[tid + o];
                if (ov > rmax[tid] || (ov == rmax[tid] && oi < rarg[tid])) {
                    rmax[tid] = ov; rarg[tid] = oi;
                }
            }
            __syncthreads();
        }
        if (tid == 0) {
            idx_out[row * TOPK + t] = rarg[0];
            s[rarg[0]] = -INFINITY;
        }
        __syncthreads();
    }
}

// ----------------------------------------------------------------------------
// Sparse cross-attention: per (token,head), softmax over the 32 gathered keys.
// One warp per head; block = 4 warps (4 heads), grid (NTOK, NH/4).
// ----------------------------------------------------------------------------
__global__ void __launch_bounds__(128) cross_attn_kernel(
    const float* __restrict__ q, const float* __restrict__ K,
    const float* __restrict__ V, const int* __restrict__ idx,
    float* __restrict__ out)
{
    int row = blockIdx.x;                 // b*NP + query
    int b = row >> 7;                     // /NP
    int warp = threadIdx.x >> 5, lane = threadIdx.x & 31;
    int h = blockIdx.y * 4 + warp;

    __shared__ float qv[4][HD];
    __shared__ float ps[4][TOPK];
    __shared__ int   id[4][TOPK];

    const float* qr = q + (long)row * D + h * HD;
    qv[warp][lane] = qr[lane];
    qv[warp][lane + 32] = qr[lane + 32];
    int ix = idx[row * TOPK + lane];
    id[warp][lane] = ix;
    __syncwarp();

    const float* kr = K + ((long)(b * MNP + ix)) * D + h * HD;
    float s = 0.f;
#pragma unroll
    for (int d = 0; d < HD; d++) s = fmaf(qv[warp][d], kr[d], s);
    s *= 0.125f;  // 1/sqrt(64)

    float m = s;
#pragma unroll
    for (int o = 16; o > 0; o >>= 1) m = fmaxf(m, __shfl_xor_sync(0xffffffffu, m, o));
    float e = expf(s - m);
    float sum = e;
#pragma unroll
    for (int o = 16; o > 0; o >>= 1) sum += __shfl_xor_sync(0xffffffffu, sum, o);
    ps[warp][lane] = e / sum;
    __syncwarp();

    float acc0 = 0.f, acc1 = 0.f;
#pragma unroll
    for (int j = 0; j < TOPK; j++) {
        const float* vr = V + ((long)(b * MNP + id[warp][j])) * D + h * HD;
        float p = ps[warp][j];
        acc0 = fmaf(p, vr[lane], acc0);
        acc1 = fmaf(p, vr[lane + 32], acc1);
    }
    float* orow = out + (long)row * D + h * HD;
    orow[lane] = acc0;
    orow[lane + 32] = acc1;
}

// ----------------------------------------------------------------------------
// Dense self-attention over NP=128 keys. Block per (token,head), 128 threads.
// qk buffer layout: [token][0:D]=q, [token][D:2D]=k.
// ----------------------------------------------------------------------------
__global__ void __launch_bounds__(128) self_attn_kernel(
    const float* __restrict__ qk, const float* __restrict__ v,
    float* __restrict__ out)
{
    int row = blockIdx.x;        // b*NP + query
    int b = row >> 7;
    int h = blockIdx.y;
    int tid = threadIdx.x;

    __shared__ float qv[HD];
    __shared__ float sc[NP];
    __shared__ float red[128];

    const float* qr = qk + (long)row * (2 * D) + h * HD;
    if (tid < HD) qv[tid] = qr[tid];
    __syncthreads();

    const float* kr = qk + (long)(b * NP + tid) * (2 * D) + D + h * HD;
    float s = 0.f;
#pragma unroll
    for (int d = 0; d < HD; d++) s = fmaf(qv[d], kr[d], s);
    s *= 0.125f;

    red[tid] = s; __syncthreads();
    for (int o = 64; o > 0; o >>= 1) {
        if (tid < o) red[tid] = fmaxf(red[tid], red[tid + o]);
        __syncthreads();
    }
    float m = red[0]; __syncthreads();
    float e = expf(s - m);
    sc[tid] = e;
    red[tid] = e; __syncthreads();
    for (int o = 64; o > 0; o >>= 1) {
        if (tid < o) red[tid] += red[tid + o];
        __syncthreads();
    }
    float inv = 1.f / red[0];

    if (tid < HD) {
        float acc = 0.f;
        for (int j = 0; j < NP; j++)
            acc = fmaf(sc[j], v[(long)(b * NP + j) * D + h * HD + tid], acc);
        out[(long)row * D + h * HD + tid] = acc * inv;
    }
}

// ----------------------------------------------------------------------------
// BatchNorm stats over all 2048 tokens -> fused per-feature scale/shift.
// ----------------------------------------------------------------------------
__global__ void __launch_bounds__(256) bn_stats_kernel(
    const float* __restrict__ x, const float* __restrict__ g,
    const float* __restrict__ b, float* __restrict__ scale,
    float* __restrict__ shift)
{
    int f = blockIdx.x, tid = threadIdx.x;
    float s = 0.f, sq = 0.f;
    for (int r = tid; r < NTOK; r += 256) {
        float v = x[(long)r * D + f];
        s += v; sq += v * v;
    }
    __shared__ float rs[256], rq[256];
    rs[tid] = s; rq[tid] = sq;
    __syncthreads();
    for (int o = 128; o > 0; o >>= 1) {
        if (tid < o) { rs[tid] += rs[tid + o]; rq[tid] += rq[tid + o]; }
        __syncthreads();
    }
    if (tid == 0) {
        float mu = rs[0] * (1.f / NTOK);
        float var = rq[0] * (1.f / NTOK) - mu * mu;
        float rstd = rsqrtf(var + EPS);
        float sc = rstd * g[f];
        scale[f] = sc;
        shift[f] = b[f] - mu * sc;
    }
}

// ----------------------------------------------------------------------------
// Host orchestration
// ----------------------------------------------------------------------------
extern "C" void kernel_launch(void* const* d_in, const int* in_sizes, int n_in,
                              void* d_out, int out_size)
{
    const float* tgt      = (const float*)d_in[0];
    const float* memory   = (const float*)d_in[1];
    const float* qpos     = (const float*)d_in[2];
    const float* kpos     = (const float*)d_in[3];
    const float* norm0_g  = (const float*)d_in[4];
    const float* norm0_b  = (const float*)d_in[5];
    const float* l1_w     = (const float*)d_in[6];
    const float* l1_b     = (const float*)d_in[7];
    const float* l2_w     = (const float*)d_in[8];
    const float* l2_b     = (const float*)d_in[9];
    const float* l3_w     = (const float*)d_in[10];
    const float* l3_b     = (const float*)d_in[11];
    const float* n1_g     = (const float*)d_in[12];
    const float* n1_b     = (const float*)d_in[13];
    const float* n2_g     = (const float*)d_in[14];
    const float* n2_b     = (const float*)d_in[15];
    const float* n3_g     = (const float*)d_in[16];
    const float* n3_b     = (const float*)d_in[17];
    const float* sa_in_w  = (const float*)d_in[18];
    const float* sa_in_b  = (const float*)d_in[19];
    const float* sa_out_w = (const float*)d_in[20];
    const float* sa_out_b = (const float*)d_in[21];
    const float* ff1_w    = (const float*)d_in[22];
    const float* ff1_b    = (const float*)d_in[23];
    const float* ff2_w    = (const float*)d_in[24];
    const float* ff2_b    = (const float*)d_in[25];
    const float* bn_g     = (const float*)d_in[26];
    const float* bn_b     = (const float*)d_in[27];
    const float* cls_w    = (const float*)d_in[28];

    float *x, *tmp, *q, *qk, *v, *attn, *Kb, *Vb, *sims, *minv, *h1, *bnsc, *bnsh;
    int* idx;
    cudaGetSymbolAddress((void**)&x,    g_x);
    cudaGetSymbolAddress((void**)&tmp,  g_tmp);
    cudaGetSymbolAddress((void**)&q,    g_q);
    cudaGetSymbolAddress((void**)&qk,   g_qk);
    cudaGetSymbolAddress((void**)&v,    g_v);
    cudaGetSymbolAddress((void**)&attn, g_attn);
    cudaGetSymbolAddress((void**)&Kb,   g_K);
    cudaGetSymbolAddress((void**)&Vb,   g_V);
    cudaGetSymbolAddress((void**)&sims, g_sims);
    cudaGetSymbolAddress((void**)&idx,  g_idx);
    cudaGetSymbolAddress((void**)&minv, g_minv);
    cudaGetSymbolAddress((void**)&h1,   g_h1);
    cudaGetSymbolAddress((void**)&bnsc, g_bnscale);
    cudaGetSymbolAddress((void**)&bnsh, g_bnshift);

    // memory row norms (constant across layers)
    rownorm_kernel<<<NMEM, 256>>>(memory, minv);

    // x = LN(tgt)
    ln_kernel<<<NTOK, 256>>>(tgt, nullptr, norm0_g, norm0_b, x);

    for (int l = 0; l < NLAYERS; l++) {
        const float* l1w = l1_w + (long)l * D * D;
        const float* l1bb = l1_b + (long)l * D;
        const float* l2w = l2_w + (long)l * D * D;
        const float* l2bb = l2_b + (long)l * D;
        const float* l3w = l3_w + (long)l * D * D;
        const float* l3bb = l3_b + (long)l * D;
        const float* saw = sa_in_w + (long)l * 3 * D * D;
        const float* sab = sa_in_b + (long)l * 3 * D;
        const float* sow = sa_out_w + (long)l * D * D;
        const float* sob = sa_out_b + (long)l * D;
        const float* f1w = ff1_w + (long)l * DFF * D;
        const float* f1b = ff1_b + (long)l * DFF;
        const float* f2w = ff2_w + (long)l * D * DFF;
        const float* f2b = ff2_b + (long)l * D;

        // sims[b] = x[b] @ memory[b]^T   (batched 128x2048x768)
        gemm_kernel<0><<<dim3(MNP / 128, 1, BS), 256>>>(
            x, nullptr, nullptr, nullptr, memory, nullptr, sims,
            NP, MNP, D, (long)NP * D, (long)MNP * D, (long)NP * MNP);

        topk_kernel<<<NTOK, 256>>>(sims, minv, idx);

        // q = (x + qpos) @ l1_w^T + b
        gemm_kernel<1><<<dim3(D / 128, NTOK / 128, 1), 256>>>(
            x, qpos, nullptr, nullptr, l1w, l1bb, q, NTOK, D, D, 0, 0, 0);

        // K = (mem + kpos) @ l2_w^T + b ; V = mem @ l3_w^T + b
        gemm_kernel<1><<<dim3(D / 128, NMEM / 128, 1), 256>>>(
            memory, kpos, nullptr, nullptr, l2w, l2bb, Kb, NMEM, D, D, 0, 0, 0);
        gemm_kernel<0><<<dim3(D / 128, NMEM / 128, 1), 256>>>(
            memory, nullptr, nullptr, nullptr, l3w, l3bb, Vb, NMEM, D, D, 0, 0, 0);

        // sparse cross-attention (32 keys/query), out -> attn
        cross_attn_kernel<<<dim3(NTOK, NH / 4), 128>>>(q, Kb, Vb, idx, attn);

        // x = LN(x + attn, n1)
        ln_kernel<<<NTOK, 256>>>(x, attn, n1_g + (long)l * D, n1_b + (long)l * D, x);

        // self-attn: [q;k] = (x+qpos) @ [wq;wk]^T ; v = x @ wv^T
        gemm_kernel<1><<<dim3((2 * D) / 128, NTOK / 128, 1), 256>>>(
            x, qpos, nullptr, nullptr, saw, sab, qk, NTOK, 2 * D, D, 0, 0, 0);
        gemm_kernel<0><<<dim3(D / 128, NTOK / 128, 1), 256>>>(
            x, nullptr, nullptr, nullptr, saw + (long)2 * D * D, sab + 2 * D,
            v, NTOK, D, D, 0, 0, 0);

        self_attn_kernel<<<dim3(NTOK, NH), 128>>>(qk, v, attn);

        // out projection
        gemm_kernel<0><<<dim3(D / 128, NTOK / 128, 1), 256>>>(
            attn, nullptr, nullptr, nullptr, sow, sob, tmp, NTOK, D, D, 0, 0, 0);

        // x = LN(x + tmp, n2)
        ln_kernel<<<NTOK, 256>>>(x, tmp, n2_g + (long)l * D, n2_b + (long)l * D, x);

        // FFN: h1 = gelu(x @ ff1^T + b1) ; tmp = h1 @ ff2^T + b2
        gemm_kernel<4><<<dim3(DFF / 128, NTOK / 128, 1), 256>>>(
            x, nullptr, nullptr, nullptr, f1w, f1b, h1, NTOK, DFF, D, 0, 0, 0);
        gemm_kernel<0><<<dim3(D / 128, NTOK / 128, 1), 256>>>(
            h1, nullptr, nullptr, nullptr, f2w, f2b, tmp, NTOK, D, DFF, 0, 0, 0);

        // x = LN(x + tmp, n3)
        ln_kernel<<<NTOK, 256>>>(x, tmp, n3_g + (long)l * D, n3_b + (long)l * D, x);
    }

    // Final: batchnorm over tokens, then cls head
    bn_stats_kernel<<<D, 256>>>(x, bn_g, bn_b, bnsc, bnsh);

    float* out = (float*)d_out;
    long xsz = (long)NTOK * D;        // 1,572,864
    long csz = (long)NTOK * NC;       // 1,538,048

    if ((long)out_size >= xsz + csz) {
        // output = concat(x, cls)
        cudaMemcpyAsync(out, x, sizeof(float) * xsz, cudaMemcpyDeviceToDevice, 0);
        gemm_kernel<2><<<dim3((NC + 127) / 128, NTOK / 128, 1), 256>>>(
            x, nullptr, bnsc, bnsh, cls_w, nullptr, out + xsz,
            NTOK, NC, D, 0, 0, 0);
    } else if ((long)out_size == csz) {
        gemm_kernel<2><<<dim3((NC + 127) / 128, NTOK / 128, 1), 256>>>(
            x, nullptr, bnsc, bnsh, cls_w, nullptr, out,
            NTOK, NC, D, 0, 0, 0);
    } else {
        cudaMemcpyAsync(out, x, sizeof(float) * ((long)out_size < xsz ? out_size : xsz),
                        cudaMemcpyDeviceToDevice, 0);
    }
}

// round 4
// speedup vs baseline: 1.5724x; 1.5724x over previous
#include <cuda_runtime.h>
#include <cuda_bf16.h>
#include <math.h>

#define BS   16
#define NP   128
#define MNP  2048
#define D    768
#define NH   12
#define HD   64
#define DFF  2048
#define NLAYERS 2
#define TOPK 32
#define NC   751
#define NTOK (BS*NP)    // 2048
#define NMEM (BS*MNP)   // 32768
#define EPS  1e-5f

// ----------------------------------------------------------------------------
// Scratch (static device globals; no runtime allocation)
// ----------------------------------------------------------------------------
__device__ float g_x   [NTOK*(long)D];
__device__ float g_tmp [NTOK*(long)D];
__device__ float g_q   [NTOK*(long)D];
__device__ float g_qk  [NTOK*(long)(2*D)];
__device__ float g_v   [NTOK*(long)D];
__device__ float g_attn[NTOK*(long)D];
__device__ float g_K   [NMEM*(long)D];
__device__ float g_V   [NMEM*(long)D];
__device__ float g_sims[NTOK*(long)MNP];
__device__ int   g_idx [NTOK*TOPK];
__device__ float g_minv[NMEM];
__device__ float g_h1  [NTOK*(long)DFF];
__device__ float g_bnscale[D];
__device__ float g_bnshift[D];

// ----------------------------------------------------------------------------
// FP32 scalar GEMM (exact path for sims -> top-k selection stability).
// C[M,N] = A[M,K] @ B[N,K]^T. 128x128 tile, 8x8 per thread.
// ----------------------------------------------------------------------------
__global__ void __launch_bounds__(256) f32_gemm_kernel(
    const float* __restrict__ A, const float* __restrict__ B,
    float* __restrict__ C, int M, int N, int K,
    long sA, long sB, long sC)
{
    constexpr int BM = 128, BN = 128, BK = 8;
    int bz = blockIdx.z;
    A += bz * sA; B += bz * sB; C += bz * sC;
    int bm = blockIdx.y * BM, bn = blockIdx.x * BN;

    __shared__ float As[BK][BM + 4];
    __shared__ float Bs[BK][BN + 4];

    int tid = threadIdx.x;
    int tx = tid & 15, ty = tid >> 4;

    float acc[8][8];
#pragma unroll
    for (int i = 0; i < 8; i++)
#pragma unroll
        for (int j = 0; j < 8; j++) acc[i][j] = 0.f;

    for (int k0 = 0; k0 < K; k0 += BK) {
#pragma unroll
        for (int l = 0; l < 4; l++) {
            int lin = tid + l * 256;
            int kk = lin & 7, r = lin >> 3;
            int m = bm + r;
            As[kk][r] = (m < M) ? A[(long)m * K + k0 + kk] : 0.f;
        }
#pragma unroll
        for (int l = 0; l < 4; l++) {
            int lin = tid + l * 256;
            int kk = lin & 7, r = lin >> 3;
            int n = bn + r;
            Bs[kk][r] = (n < N) ? B[(long)n * K + k0 + kk] : 0.f;
        }
        __syncthreads();
#pragma unroll
        for (int k = 0; k < BK; k++) {
            float a[8], b[8];
            *(float4*)&a[0] = *(const float4*)&As[k][ty * 8];
            *(float4*)&a[4] = *(const float4*)&As[k][ty * 8 + 4];
            *(float4*)&b[0] = *(const float4*)&Bs[k][tx * 8];
            *(float4*)&b[4] = *(const float4*)&Bs[k][tx * 8 + 4];
#pragma unroll
            for (int i = 0; i < 8; i++)
#pragma unroll
                for (int j = 0; j < 8; j++)
                    acc[i][j] = fmaf(a[i], b[j], acc[i][j]);
        }
        __syncthreads();
    }
#pragma unroll
    for (int i = 0; i < 8; i++) {
        int m = bm + ty * 8 + i;
        if (m >= M) continue;
#pragma unroll
        for (int j = 0; j < 8; j++) {
            int n = bn + tx * 8 + j;
            if (n < N) C[(long)m * N + n] = acc[i][j];
        }
    }
}

// ----------------------------------------------------------------------------
// bf16 helpers
// ----------------------------------------------------------------------------
__device__ __forceinline__ unsigned pack2(float x, float y) {
    __nv_bfloat162 t = __floats2bfloat162_rn(x, y);
    return *(unsigned*)&t;
}

__device__ __forceinline__ void mma_bf16(float c[4],
    unsigned a0, unsigned a1, unsigned a2, unsigned a3,
    unsigned b0, unsigned b1)
{
    asm("mma.sync.aligned.m16n8k16.row.col.f32.bf16.bf16.f32 "
        "{%0,%1,%2,%3}, {%4,%5,%6,%7}, {%8,%9}, {%0,%1,%2,%3};"
        : "+f"(c[0]), "+f"(c[1]), "+f"(c[2]), "+f"(c[3])
        : "r"(a0), "r"(a1), "r"(a2), "r"(a3), "r"(b0), "r"(b1));
}

// ----------------------------------------------------------------------------
// Tensor-core GEMM with bf16x3 fp32 emulation:
// C[M,N] = op(A)[M,K] @ B[N,K]^T (+bias) (+gelu)
// MODE bit0: A += A2 ; bit1: BN affine on A per-k ; bit2: GELU epilogue
// ----------------------------------------------------------------------------
template<int MODE>
__global__ void __launch_bounds__(256) tc_gemm_kernel(
    const float* __restrict__ A, const float* __restrict__ A2,
    const float* __restrict__ ascale, const float* __restrict__ ashift,
    const float* __restrict__ B, const float* __restrict__ bias,
    float* __restrict__ C, int M, int N, int K,
    long sA, long sB, long sC)
{
    constexpr int BM = 128, BN = 128;
    int bz = blockIdx.z;
    A += bz * sA;
    if (MODE & 1) A2 += bz * sA;
    B += bz * sB;
    C += bz * sC;
    const int bm = blockIdx.y * BM, bn = blockIdx.x * BN;

    __shared__ unsigned Ah[2][8][BM + 4];
    __shared__ unsigned Al[2][8][BM + 4];
    __shared__ unsigned Bh[2][8][BN + 4];
    __shared__ unsigned Bl[2][8][BN + 4];

    const int tid  = threadIdx.x;
    const int wid  = tid >> 5;
    const int lane = tid & 31;
    const int wm   = wid & 1;
    const int wn   = wid >> 1;
    const int qm   = lane >> 2;
    const int qk   = lane & 3;

    float acc[4][4][4];
#pragma unroll
    for (int mt = 0; mt < 4; mt++)
#pragma unroll
        for (int nt = 0; nt < 4; nt++)
#pragma unroll
            for (int r = 0; r < 4; r++) acc[mt][nt][r] = 0.f;

    auto split2 = [](float x, float y, unsigned& hi, unsigned& lo) {
        float xh = __bfloat162float(__float2bfloat16_rn(x));
        float yh = __bfloat162float(__float2bfloat16_rn(y));
        hi = pack2(xh, yh);
        lo = pack2(x - xh, y - yh);
    };

    auto loadTile = [&](int buf, int k0) {
#pragma unroll
        for (int l = 0; l < 2; l++) {
            int lin = tid + l * 256;
            int r   = lin >> 2;
            int c4  = (lin & 3) * 4;
            long aoff = (long)(bm + r) * K + k0 + c4;
            float4 av = *(const float4*)(A + aoff);
            if (MODE & 1) {
                float4 p = *(const float4*)(A2 + aoff);
                av.x += p.x; av.y += p.y; av.z += p.z; av.w += p.w;
            }
            if (MODE & 2) {
                av.x = av.x * ascale[k0 + c4 + 0] + ashift[k0 + c4 + 0];
                av.y = av.y * ascale[k0 + c4 + 1] + ashift[k0 + c4 + 1];
                av.z = av.z * ascale[k0 + c4 + 2] + ashift[k0 + c4 + 2];
                av.w = av.w * ascale[k0 + c4 + 3] + ashift[k0 + c4 + 3];
            }
            unsigned h0, l0, h1, l1;
            split2(av.x, av.y, h0, l0);
            split2(av.z, av.w, h1, l1);
            int kp = c4 >> 1;
            Ah[buf][kp    ][r] = h0; Al[buf][kp    ][r] = l0;
            Ah[buf][kp + 1][r] = h1; Al[buf][kp + 1][r] = l1;
            int n = bn + r;
            float4 bv = make_float4(0.f, 0.f, 0.f, 0.f);
            if (n < N) bv = *(const float4*)(B + (long)n * K + k0 + c4);
            split2(bv.x, bv.y, h0, l0);
            split2(bv.z, bv.w, h1, l1);
            Bh[buf][kp    ][r] = h0; Bl[buf][kp    ][r] = l0;
            Bh[buf][kp + 1][r] = h1; Bl[buf][kp + 1][r] = l1;
        }
    };

    auto compute = [&](int buf) {
        unsigned ah[4][4], al[4][4], bh[4][2], bl[4][2];
#pragma unroll
        for (int mt = 0; mt < 4; mt++) {
            int r0 = wm * 64 + mt * 16 + qm;
            ah[mt][0] = Ah[buf][qk    ][r0];     al[mt][0] = Al[buf][qk    ][r0];
            ah[mt][1] = Ah[buf][qk    ][r0 + 8]; al[mt][1] = Al[buf][qk    ][r0 + 8];
            ah[mt][2] = Ah[buf][qk + 4][r0];     al[mt][2] = Al[buf][qk + 4][r0];
            ah[mt][3] = Ah[buf][qk + 4][r0 + 8]; al[mt][3] = Al[buf][qk + 4][r0 + 8];
        }
#pragma unroll
        for (int nt = 0; nt < 4; nt++) {
            int c = wn * 32 + nt * 8 + qm;
            bh[nt][0] = Bh[buf][qk    ][c]; bl[nt][0] = Bl[buf][qk    ][c];
            bh[nt][1] = Bh[buf][qk + 4][c]; bl[nt][1] = Bl[buf][qk + 4][c];
        }
#pragma unroll
        for (int mt = 0; mt < 4; mt++)
#pragma unroll
            for (int nt = 0; nt < 4; nt++) {
                mma_bf16(acc[mt][nt], ah[mt][0], ah[mt][1], ah[mt][2], ah[mt][3],
                         bh[nt][0], bh[nt][1]);
                mma_bf16(acc[mt][nt], ah[mt][0], ah[mt][1], ah[mt][2], ah[mt][3],
                         bl[nt][0], bl[nt][1]);
                mma_bf16(acc[mt][nt], al[mt][0], al[mt][1], al[mt][2], al[mt][3],
                         bh[nt][0], bh[nt][1]);
            }
    };

    loadTile(0, 0);
    __syncthreads();
    int cur = 0;
    for (int k0 = 0; k0 < K; k0 += 16) {
        int nxt = cur ^ 1;
        if (k0 + 16 < K) loadTile(nxt, k0 + 16);
        compute(cur);
        __syncthreads();
        cur = nxt;
    }

    const int qn2 = (lane & 3) * 2;
#pragma unroll
    for (int mt = 0; mt < 4; mt++) {
        int r0 = bm + wm * 64 + mt * 16 + qm;
#pragma unroll
        for (int nt = 0; nt < 4; nt++) {
            int c0 = bn + wn * 32 + nt * 8 + qn2;
            float v[4];
            v[0] = acc[mt][nt][0]; v[1] = acc[mt][nt][1];
            v[2] = acc[mt][nt][2]; v[3] = acc[mt][nt][3];
            float b0 = 0.f, b1 = 0.f;
            if (bias) {
                if (c0 < N)     b0 = bias[c0];
                if (c0 + 1 < N) b1 = bias[c0 + 1];
            }
            v[0] += b0; v[1] += b1; v[2] += b0; v[3] += b1;
            if (MODE & 4) {
#pragma unroll
                for (int r = 0; r < 4; r++)
                    v[r] = 0.5f * v[r] * (1.f + erff(v[r] * 0.70710678118654752f));
            }
            if (c0 < N) {
                C[(long)r0 * N + c0]       = v[0];
                C[(long)(r0 + 8) * N + c0] = v[2];
            }
            if (c0 + 1 < N) {
                C[(long)r0 * N + c0 + 1]       = v[1];
                C[(long)(r0 + 8) * N + c0 + 1] = v[3];
            }
        }
    }
}

// ----------------------------------------------------------------------------
// LayerNorm over last dim (D=768)
// ----------------------------------------------------------------------------
__global__ void __launch_bounds__(256) ln_kernel(
    const float* __restrict__ x, const float* __restrict__ add,
    const float* __restrict__ g, const float* __restrict__ b,
    float* __restrict__ out)
{
    int row = blockIdx.x, tid = threadIdx.x;
    const float* xr = x + (long)row * D;
    float vals[3];
    float s = 0.f, sq = 0.f;
#pragma unroll
    for (int i = 0; i < 3; i++) {
        int c = tid + i * 256;
        float v = xr[c];
        if (add) v += add[(long)row * D + c];
        vals[i] = v; s += v; sq += v * v;
    }
    __shared__ float rs[256], rq[256];
    rs[tid] = s; rq[tid] = sq;
    __syncthreads();
    for (int o = 128; o > 0; o >>= 1) {
        if (tid < o) { rs[tid] += rs[tid + o]; rq[tid] += rq[tid + o]; }
        __syncthreads();
    }
    float mu = rs[0] * (1.f / D);
    float var = rq[0] * (1.f / D) - mu * mu;
    float rstd = rsqrtf(var + EPS);
    float* orow = out + (long)row * D;
#pragma unroll
    for (int i = 0; i < 3; i++) {
        int c = tid + i * 256;
        orow[c] = (vals[i] - mu) * rstd * g[c] + b[c];
    }
}

__global__ void __launch_bounds__(256) rownorm_kernel(
    const float* __restrict__ m, float* __restrict__ minv)
{
    int row = blockIdx.x, tid = threadIdx.x;
    float s = 0.f;
#pragma unroll
    for (int i = 0; i < 3; i++) {
        float v = m[(long)row * D + tid + i * 256];
        s += v * v;
    }
    __shared__ float rs[256];
    rs[tid] = s; __syncthreads();
    for (int o = 128; o > 0; o >>= 1) {
        if (tid < o) rs[tid] += rs[tid + o];
        __syncthreads();
    }
    if (tid == 0) minv[row] = rsqrtf(rs[0]);
}

// ----------------------------------------------------------------------------
// Top-32 per query row (iterative block argmax over smem copy).
// ----------------------------------------------------------------------------
__global__ void __launch_bounds__(256) topk_kernel(
    const float* __restrict__ sims, const float* __restrict__ minv,
    int* __restrict__ idx_out)
{
    int row = blockIdx.x;
    int b = row / NP;
    int tid = threadIdx.x;
    __shared__ float s[MNP];
    __shared__ float rmax[256];
    __shared__ int   rarg[256];
    for (int i = tid; i < MNP; i += 256)
        s[i] = sims[(long)row * MNP + i] * minv[b * MNP + i];
    __syncthreads();
    for (int t = 0; t < TOPK; t++) {
        float best = -INFINITY; int bi = 0x7fffffff;
        for (int i = tid; i < MNP; i += 256) {
            float v = s[i];
            if (v > best) { best = v; bi = i; }
        }
        rmax[tid] = best; rarg[tid] = bi;
        __syncthreads();
        for (int o = 128; o > 0; o >>= 1) {
            if (tid < o) {
                float ov = rmax[tid + o]; int oi = rarg[tid + o];
                if (ov > rmax[tid] || (ov == rmax[tid] && oi < rarg[tid])) {
                    rmax[tid] = ov; rarg[tid] = oi;
                }
            }
            __syncthreads();
        }
        if (tid == 0) {
            idx_out[row * TOPK + t] = rarg[0];
            s[rarg[0]] = -INFINITY;
        }
        __syncthreads();
    }
}

// ----------------------------------------------------------------------------
// Sparse cross-attention (32 gathered keys per query,head)
// ----------------------------------------------------------------------------
__global__ void __launch_bounds__(128) cross_attn_kernel(
    const float* __restrict__ q, const float* __restrict__ K,
    const float* __restrict__ V, const int* __restrict__ idx,
    float* __restrict__ out)
{
    int row = blockIdx.x;
    int b = row >> 7;
    int warp = threadIdx.x >> 5, lane = threadIdx.x & 31;
    int h = blockIdx.y * 4 + warp;

    __shared__ float qv[4][HD];
    __shared__ float ps[4][TOPK];
    __shared__ int   id[4][TOPK];

    const float* qr = q + (long)row * D + h * HD;
    qv[warp][lane] = qr[lane];
    qv[warp][lane + 32] = qr[lane + 32];
    int ix = idx[row * TOPK + lane];
    id[warp][lane] = ix;
    __syncwarp();

    const float* kr = K + ((long)(b * MNP + ix)) * D + h * HD;
    float s = 0.f;
#pragma unroll
    for (int d = 0; d < HD; d++) s = fmaf(qv[warp][d], kr[d], s);
    s *= 0.125f;

    float m = s;
#pragma unroll
    for (int o = 16; o > 0; o >>= 1) m = fmaxf(m, __shfl_xor_sync(0xffffffffu, m, o));
    float e = expf(s - m);
    float sum = e;
#pragma unroll
    for (int o = 16; o > 0; o >>= 1) sum += __shfl_xor_sync(0xffffffffu, sum, o);
    ps[warp][lane] = e / sum;
    __syncwarp();

    float acc0 = 0.f, acc1 = 0.f;
#pragma unroll
    for (int j = 0; j < TOPK; j++) {
        const float* vr = V + ((long)(b * MNP + id[warp][j])) * D + h * HD;
        float p = ps[warp][j];
        acc0 = fmaf(p, vr[lane], acc0);
        acc1 = fmaf(p, vr[lane + 32], acc1);
    }
    float* orow = out + (long)row * D + h * HD;
    orow[lane] = acc0;
    orow[lane + 32] = acc1;
}

// ----------------------------------------------------------------------------
// Dense self-attention over NP=128 keys
// ----------------------------------------------------------------------------
__global__ void __launch_bounds__(128) self_attn_kernel(
    const float* __restrict__ qk, const float* __restrict__ v,
    float* __restrict__ out)
{
    int row = blockIdx.x;
    int b = row >> 7;
    int h = blockIdx.y;
    int tid = threadIdx.x;

    __shared__ float qv[HD];
    __shared__ float sc[NP];
    __shared__ float red[128];

    const float* qr = qk + (long)row * (2 * D) + h * HD;
    if (tid < HD) qv[tid] = qr[tid];
    __syncthreads();

    const float* kr = qk + (long)(b * NP + tid) * (2 * D) + D + h * HD;
    float s = 0.f;
#pragma unroll
    for (int d = 0; d < HD; d++) s = fmaf(qv[d], kr[d], s);
    s *= 0.125f;

    red[tid] = s; __syncthreads();
    for (int o = 64; o > 0; o >>= 1) {
        if (tid < o) red[tid] = fmaxf(red[tid], red[tid + o]);
        __syncthreads();
    }
    float m = red[0]; __syncthreads();
    float e = expf(s - m);
    sc[tid] = e;
    red[tid] = e; __syncthreads();
    for (int o = 64; o > 0; o >>= 1) {
        if (tid < o) red[tid] += red[tid + o];
        __syncthreads();
    }
    float inv = 1.f / red[0];

    if (tid < HD) {
        float acc = 0.f;
        for (int j = 0; j < NP; j++)
            acc = fmaf(sc[j], v[(long)(b * NP + j) * D + h * HD + tid], acc);
        out[(long)row * D + h * HD + tid] = acc * inv;
    }
}

// ----------------------------------------------------------------------------
// BatchNorm stats -> fused scale/shift
// ----------------------------------------------------------------------------
__global__ void __launch_bounds__(256) bn_stats_kernel(
    const float* __restrict__ x, const float* __restrict__ g,
    const float* __restrict__ b, float* __restrict__ scale,
    float* __restrict__ shift)
{
    int f = blockIdx.x, tid = threadIdx.x;
    float s = 0.f, sq = 0.f;
    for (int r = tid; r < NTOK; r += 256) {
        float v = x[(long)r * D + f];
        s += v; sq += v * v;
    }
    __shared__ float rs[256], rq[256];
    rs[tid] = s; rq[tid] = sq;
    __syncthreads();
    for (int o = 128; o > 0; o >>= 1) {
        if (tid < o) { rs[tid] += rs[tid + o]; rq[tid] += rq[tid + o]; }
        __syncthreads();
    }
    if (tid == 0) {
        float mu = rs[0] * (1.f / NTOK);
        float var = rq[0] * (1.f / NTOK) - mu * mu;
        float rstd = rsqrtf(var + EPS);
        float sc = rstd * g[f];
        scale[f] = sc;
        shift[f] = b[f] - mu * sc;
    }
}

// ----------------------------------------------------------------------------
// Host orchestration
// ----------------------------------------------------------------------------
extern "C" void kernel_launch(void* const* d_in, const int* in_sizes, int n_in,
                              void* d_out, int out_size)
{
    const float* tgt      = (const float*)d_in[0];
    const float* memory   = (const float*)d_in[1];
    const float* qpos     = (const float*)d_in[2];
    const float* kpos     = (const float*)d_in[3];
    const float* norm0_g  = (const float*)d_in[4];
    const float* norm0_b  = (const float*)d_in[5];
    const float* l1_w     = (const float*)d_in[6];
    const float* l1_b     = (const float*)d_in[7];
    const float* l2_w     = (const float*)d_in[8];
    const float* l2_b     = (const float*)d_in[9];
    const float* l3_w     = (const float*)d_in[10];
    const float* l3_b     = (const float*)d_in[11];
    const float* n1_g     = (const float*)d_in[12];
    const float* n1_b     = (const float*)d_in[13];
    const float* n2_g     = (const float*)d_in[14];
    const float* n2_b     = (const float*)d_in[15];
    const float* n3_g     = (const float*)d_in[16];
    const float* n3_b     = (const float*)d_in[17];
    const float* sa_in_w  = (const float*)d_in[18];
    const float* sa_in_b  = (const float*)d_in[19];
    const float* sa_out_w = (const float*)d_in[20];
    const float* sa_out_b = (const float*)d_in[21];
    const float* ff1_w    = (const float*)d_in[22];
    const float* ff1_b    = (const float*)d_in[23];
    const float* ff2_w    = (const float*)d_in[24];
    const float* ff2_b    = (const float*)d_in[25];
    const float* bn_g     = (const float*)d_in[26];
    const float* bn_b     = (const float*)d_in[27];
    const float* cls_w    = (const float*)d_in[28];

    float *x, *tmp, *q, *qk, *v, *attn, *Kb, *Vb, *sims, *minv, *h1, *bnsc, *bnsh;
    int* idx;
    cudaGetSymbolAddress((void**)&x,    g_x);
    cudaGetSymbolAddress((void**)&tmp,  g_tmp);
    cudaGetSymbolAddress((void**)&q,    g_q);
    cudaGetSymbolAddress((void**)&qk,   g_qk);
    cudaGetSymbolAddress((void**)&v,    g_v);
    cudaGetSymbolAddress((void**)&attn, g_attn);
    cudaGetSymbolAddress((void**)&Kb,   g_K);
    cudaGetSymbolAddress((void**)&Vb,   g_V);
    cudaGetSymbolAddress((void**)&sims, g_sims);
    cudaGetSymbolAddress((void**)&idx,  g_idx);
    cudaGetSymbolAddress((void**)&minv, g_minv);
    cudaGetSymbolAddress((void**)&h1,   g_h1);
    cudaGetSymbolAddress((void**)&bnsc, g_bnscale);
    cudaGetSymbolAddress((void**)&bnsh, g_bnshift);

    rownorm_kernel<<<NMEM, 256>>>(memory, minv);
    ln_kernel<<<NTOK, 256>>>(tgt, nullptr, norm0_g, norm0_b, x);

    for (int l = 0; l < NLAYERS; l++) {
        const float* l1w = l1_w + (long)l * D * D;
        const float* l1bb = l1_b + (long)l * D;
        const float* l2w = l2_w + (long)l * D * D;
        const float* l2bb = l2_b + (long)l * D;
        const float* l3w = l3_w + (long)l * D * D;
        const float* l3bb = l3_b + (long)l * D;
        const float* saw = sa_in_w + (long)l * 3 * D * D;
        const float* sab = sa_in_b + (long)l * 3 * D;
        const float* sow = sa_out_w + (long)l * D * D;
        const float* sob = sa_out_b + (long)l * D;
        const float* f1w = ff1_w + (long)l * DFF * D;
        const float* f1b = ff1_b + (long)l * DFF;
        const float* f2w = ff2_w + (long)l * D * DFF;
        const float* f2b = ff2_b + (long)l * D;

        // sims[b] = x[b] @ memory[b]^T  — FP32 EXACT (top-k selection stability)
        f32_gemm_kernel<<<dim3(MNP / 128, 1, BS), 256>>>(
            x, memory, sims, NP, MNP, D,
            (long)NP * D, (long)MNP * D, (long)NP * MNP);

        topk_kernel<<<NTOK, 256>>>(sims, minv, idx);

        // q = (x + qpos) @ l1_w^T + b
        tc_gemm_kernel<1><<<dim3(D / 128, NTOK / 128, 1), 256>>>(
            x, qpos, nullptr, nullptr, l1w, l1bb, q, NTOK, D, D, 0, 0, 0);

        // K = (mem + kpos) @ l2_w^T + b ; V = mem @ l3_w^T + b
        tc_gemm_kernel<1><<<dim3(D / 128, NMEM / 128, 1), 256>>>(
            memory, kpos, nullptr, nullptr, l2w, l2bb, Kb, NMEM, D, D, 0, 0, 0);
        tc_gemm_kernel<0><<<dim3(D / 128, NMEM / 128, 1), 256>>>(
            memory, nullptr, nullptr, nullptr, l3w, l3bb, Vb, NMEM, D, D, 0, 0, 0);

        cross_attn_kernel<<<dim3(NTOK, NH / 4), 128>>>(q, Kb, Vb, idx, attn);

        ln_kernel<<<NTOK, 256>>>(x, attn, n1_g + (long)l * D, n1_b + (long)l * D, x);

        // self-attn projections
        tc_gemm_kernel<1><<<dim3((2 * D) / 128, NTOK / 128, 1), 256>>>(
            x, qpos, nullptr, nullptr, saw, sab, qk, NTOK, 2 * D, D, 0, 0, 0);
        tc_gemm_kernel<0><<<dim3(D / 128, NTOK / 128, 1), 256>>>(
            x, nullptr, nullptr, nullptr, saw + (long)2 * D * D, sab + 2 * D,
            v, NTOK, D, D, 0, 0, 0);

        self_attn_kernel<<<dim3(NTOK, NH), 128>>>(qk, v, attn);

        tc_gemm_kernel<0><<<dim3(D / 128, NTOK / 128, 1), 256>>>(
            attn, nullptr, nullptr, nullptr, sow, sob, tmp, NTOK, D, D, 0, 0, 0);

        ln_kernel<<<NTOK, 256>>>(x, tmp, n2_g + (long)l * D, n2_b + (long)l * D, x);

        // FFN
        tc_gemm_kernel<4><<<dim3(DFF / 128, NTOK / 128, 1), 256>>>(
            x, nullptr, nullptr, nullptr, f1w, f1b, h1, NTOK, DFF, D, 0, 0, 0);
        tc_gemm_kernel<0><<<dim3(D / 128, NTOK / 128, 1), 256>>>(
            h1, nullptr, nullptr, nullptr, f2w, f2b, tmp, NTOK, D, DFF, 0, 0, 0);

        ln_kernel<<<NTOK, 256>>>(x, tmp, n3_g + (long)l * D, n3_b + (long)l * D, x);
    }

    bn_stats_kernel<<<D, 256>>>(x, bn_g, bn_b, bnsc, bnsh);

    float* out = (float*)d_out;
    long xsz = (long)NTOK * D;
    long csz = (long)NTOK * NC;

    if ((long)out_size >= xsz + csz) {
        cudaMemcpyAsync(out, x, sizeof(float) * xsz, cudaMemcpyDeviceToDevice, 0);
        tc_gemm_kernel<2><<<dim3((NC + 127) / 128, NTOK / 128, 1), 256>>>(
            x, nullptr, bnsc, bnsh, cls_w, nullptr, out + xsz,
            NTOK, NC, D, 0, 0, 0);
    } else if ((long)out_size == csz) {
        tc_gemm_kernel<2><<<dim3((NC + 127) / 128, NTOK / 128, 1), 256>>>(
            x, nullptr, bnsc, bnsh, cls_w, nullptr, out,
            NTOK, NC, D, 0, 0, 0);
    } else {
        cudaMemcpyAsync(out, x, sizeof(float) * ((long)out_size < xsz ? out_size : xsz),
                        cudaMemcpyDeviceToDevice, 0);
    }
}

// round 6
// speedup vs baseline: 1.8126x; 1.1527x over previous
#include <cuda_runtime.h>
#include <cuda_bf16.h>
#include <math.h>
#include <stdint.h>

#define BS   16
#define NP   128
#define MNP  2048
#define D    768
#define NH   12
#define HD   64
#define DFF  2048
#define NLAYERS 2
#define TOPK 32
#define NC   751
#define NTOK (BS*NP)    // 2048
#define NMEM (BS*MNP)   // 32768
#define EPS  1e-5f

// ----------------------------------------------------------------------------
// Scratch (static device globals; no runtime allocation)
// ----------------------------------------------------------------------------
__device__ float g_x   [NTOK*(long)D];
__device__ float g_tmp [NTOK*(long)D];
__device__ float g_q   [NTOK*(long)D];
__device__ float g_qk  [NTOK*(long)(2*D)];
__device__ float g_v   [NTOK*(long)D];
__device__ float g_attn[NTOK*(long)D];
__device__ float g_K   [NMEM*(long)D];
__device__ float g_V   [NMEM*(long)D];
__device__ float g_sims[NTOK*(long)MNP];
__device__ int   g_idx [NTOK*TOPK];
__device__ float g_minv[NMEM];
__device__ float g_bnscale[D];
__device__ float g_bnshift[D];

// bf16 hi/lo split buffers
#define WTOTAL 15125760L
__device__ __nv_bfloat16 g_whi[WTOTAL], g_wlo[WTOTAL];
__device__ __nv_bfloat16 g_mkhi[NMEM*(long)D], g_mklo[NMEM*(long)D];   // mem+kpos
__device__ __nv_bfloat16 g_mhi [NMEM*(long)D], g_mlo [NMEM*(long)D];   // mem
__device__ __nv_bfloat16 g_xhi [NTOK*(long)D], g_xlo [NTOK*(long)D];   // x
__device__ __nv_bfloat16 g_xqhi[NTOK*(long)D], g_xqlo[NTOK*(long)D];   // x+qpos
__device__ __nv_bfloat16 g_h1hi[NTOK*(long)DFF], g_h1lo[NTOK*(long)DFF];
__device__ __nv_bfloat16 g_sahi[NTOK*(long)D], g_salo[NTOK*(long)D];   // self-attn out
__device__ __nv_bfloat16 g_cihi[NTOK*(long)D], g_cilo[NTOK*(long)D];   // cls input

// Weight split buffer offsets (elements)
#define OFF_L1    0L
#define OFF_L2    1179648L
#define OFF_L3    2359296L
#define OFF_SAIN  3538944L
#define OFF_SAOUT 7077888L
#define OFF_FF1   8257536L
#define OFF_FF2   11403264L
#define OFF_CLS   14548992L

// ----------------------------------------------------------------------------
// Helpers
// ----------------------------------------------------------------------------
__device__ __forceinline__ uint32_t smem_u32(const void* p) {
    uint32_t a;
    asm("{ .reg .u64 t; cvta.to.shared.u64 t, %1; cvt.u32.u64 %0, t; }"
        : "=r"(a) : "l"(p));
    return a;
}

#define CP_ASYNC16(dst, src) \
    asm volatile("cp.async.ca.shared.global [%0], [%1], 16;" \
                 :: "r"(dst), "l"(src) : "memory")
#define CP_COMMIT() asm volatile("cp.async.commit_group;" ::: "memory")
#define CP_WAIT(n)  asm volatile("cp.async.wait_group %0;" :: "n"(n) : "memory")

__device__ __forceinline__ void mma_bf16(float c[4],
    uint32_t a0, uint32_t a1, uint32_t a2, uint32_t a3,
    uint32_t b0, uint32_t b1)
{
    asm("mma.sync.aligned.m16n8k16.row.col.f32.bf16.bf16.f32 "
        "{%0,%1,%2,%3}, {%4,%5,%6,%7}, {%8,%9}, {%0,%1,%2,%3};"
        : "+f"(c[0]), "+f"(c[1]), "+f"(c[2]), "+f"(c[3])
        : "r"(a0), "r"(a1), "r"(a2), "r"(a3), "r"(b0), "r"(b1));
}

__device__ __forceinline__ void split1(float v, __nv_bfloat16& h, __nv_bfloat16& l) {
    __nv_bfloat16 hb = __float2bfloat16_rn(v);
    h = hb;
    l = __float2bfloat16_rn(v - __bfloat162float(hb));
}

// ----------------------------------------------------------------------------
// Split kernels (fp32 -> bf16 hi/lo)
// ----------------------------------------------------------------------------
__global__ void __launch_bounds__(256) split_kernel(
    const float* __restrict__ src,
    __nv_bfloat16* __restrict__ hi, __nv_bfloat16* __restrict__ lo, long n)
{
    long i = blockIdx.x * 256L + threadIdx.x;
    long stride = (long)gridDim.x * 256;
    for (; i < n; i += stride) {
        __nv_bfloat16 h, l;
        split1(src[i], h, l);
        hi[i] = h; lo[i] = l;
    }
}

__global__ void __launch_bounds__(256) split_add_kernel(
    const float* __restrict__ a, const float* __restrict__ b,
    __nv_bfloat16* __restrict__ hi, __nv_bfloat16* __restrict__ lo, long n)
{
    long i = blockIdx.x * 256L + threadIdx.x;
    long stride = (long)gridDim.x * 256;
    for (; i < n; i += stride) {
        __nv_bfloat16 h, l;
        split1(a[i] + b[i], h, l);
        hi[i] = h; lo[i] = l;
    }
}

__global__ void __launch_bounds__(256) split_affine_kernel(
    const float* __restrict__ src, const float* __restrict__ scale,
    const float* __restrict__ shift,
    __nv_bfloat16* __restrict__ hi, __nv_bfloat16* __restrict__ lo, long n)
{
    long i = blockIdx.x * 256L + threadIdx.x;
    long stride = (long)gridDim.x * 256;
    for (; i < n; i += stride) {
        int k = (int)(i % D);
        __nv_bfloat16 h, l;
        split1(src[i] * scale[k] + shift[k], h, l);
        hi[i] = h; lo[i] = l;
    }
}

// ----------------------------------------------------------------------------
// bf16x3 tensor-core GEMM with pre-split operands.
// C[M,N] = (Ah+Al)[M,K] @ (Bh+Bl)[N,K]^T  (3-term: AhBh + AhBl + AlBh)
// BM=128, BN template (128 or 64), BK=32, 128 threads (4 warps, 64 x BN/2 tiles)
// cp.async double-buffered. EPI: 0 = (+bias)->fp32 C ; 1 = gelu(+bias)->bf16 split
// M % 128 == 0, K % 32 == 0; N arbitrary (B rows zero-filled, stores guarded).
// ----------------------------------------------------------------------------
template<int BN, int EPI>
__global__ void __launch_bounds__(128) hgemm_kernel(
    const __nv_bfloat16* __restrict__ Ah, const __nv_bfloat16* __restrict__ Al,
    const __nv_bfloat16* __restrict__ Bh, const __nv_bfloat16* __restrict__ Bl,
    const float* __restrict__ bias,
    float* __restrict__ C,
    __nv_bfloat16* __restrict__ Chi, __nv_bfloat16* __restrict__ Clo,
    int M, int N, int K)
{
    constexpr int BM = 128;
    constexpr int NT = BN / 16;          // n8-tiles per warp
    constexpr int ROWS = BM + BN;        // A rows then B rows per part
    extern __shared__ __align__(16) __nv_bfloat16 smem[];

    const int tid  = threadIdx.x;
    const int wid  = tid >> 5;
    const int lane = tid & 31;
    const int wm   = wid & 1;            // 2 row-halves of 64
    const int wn   = wid >> 1;           // 2 col-halves of BN/2
    const int qm   = lane >> 2;
    const int qk   = lane & 3;
    const int bm = blockIdx.y * BM;
    const int bn = blockIdx.x * BN;
    const uint32_t sbase = smem_u32(smem);

    float acc[4][NT][4];
#pragma unroll
    for (int mt = 0; mt < 4; mt++)
#pragma unroll
        for (int nt = 0; nt < NT; nt++)
#pragma unroll
            for (int r = 0; r < 4; r++) acc[mt][nt][r] = 0.f;

    auto loadStage = [&](int s, int k0) {
        const uint32_t pH = sbase + (uint32_t)(s * 2 + 0) * ROWS * 80;
        const uint32_t pL = sbase + (uint32_t)(s * 2 + 1) * ROWS * 80;
#pragma unroll
        for (int c = tid; c < BM * 4; c += 128) {
            int row = c >> 2, kc = c & 3;
            long gofs = (long)(bm + row) * K + k0;
            CP_ASYNC16(pH + row * 80 + kc * 16, (const char*)(Ah + gofs) + kc * 16);
            CP_ASYNC16(pL + row * 80 + kc * 16, (const char*)(Al + gofs) + kc * 16);
        }
#pragma unroll
        for (int c = tid; c < BN * 4; c += 128) {
            int row = c >> 2, kc = c & 3;
            int n = bn + row;
            uint32_t dh = pH + (BM + row) * 80 + kc * 16;
            uint32_t dl = pL + (BM + row) * 80 + kc * 16;
            if (n < N) {
                long gofs = (long)n * K + k0;
                CP_ASYNC16(dh, (const char*)(Bh + gofs) + kc * 16);
                CP_ASYNC16(dl, (const char*)(Bl + gofs) + kc * 16);
            } else {
                uint32_t z = 0;
                asm volatile("st.shared.v4.b32 [%0], {%1,%1,%1,%1};" :: "r"(dh), "r"(z) : "memory");
                asm volatile("st.shared.v4.b32 [%0], {%1,%1,%1,%1};" :: "r"(dl), "r"(z) : "memory");
            }
        }
    };

    auto compute = [&](int s) {
        const uint32_t* SH = (const uint32_t*)smem + (long)(s * 2 + 0) * ROWS * 20;
        const uint32_t* SL = (const uint32_t*)smem + (long)(s * 2 + 1) * ROWS * 20;
#pragma unroll
        for (int kc = 0; kc < 2; kc++) {
            const int w = kc * 8 + qk;
            uint32_t ah[4][4], al[4][4];
#pragma unroll
            for (int mt = 0; mt < 4; mt++) {
                int r = wm * 64 + mt * 16 + qm;
                ah[mt][0] = SH[r * 20 + w];
                ah[mt][1] = SH[(r + 8) * 20 + w];
                ah[mt][2] = SH[r * 20 + w + 4];
                ah[mt][3] = SH[(r + 8) * 20 + w + 4];
                al[mt][0] = SL[r * 20 + w];
                al[mt][1] = SL[(r + 8) * 20 + w];
                al[mt][2] = SL[r * 20 + w + 4];
                al[mt][3] = SL[(r + 8) * 20 + w + 4];
            }
#pragma unroll
            for (int nt = 0; nt < NT; nt++) {
                int rb = BM + wn * (BN / 2) + nt * 8 + qm;
                uint32_t bh0 = SH[rb * 20 + w], bh1 = SH[rb * 20 + w + 4];
                uint32_t bl0 = SL[rb * 20 + w], bl1 = SL[rb * 20 + w + 4];
#pragma unroll
                for (int mt = 0; mt < 4; mt++) {
                    mma_bf16(acc[mt][nt], ah[mt][0], ah[mt][1], ah[mt][2], ah[mt][3], bh0, bh1);
                    mma_bf16(acc[mt][nt], ah[mt][0], ah[mt][1], ah[mt][2], ah[mt][3], bl0, bl1);
                    mma_bf16(acc[mt][nt], al[mt][0], al[mt][1], al[mt][2], al[mt][3], bh0, bh1);
                }
            }
        }
    };

    const int niter = K >> 5;
    loadStage(0, 0); CP_COMMIT();
    for (int i = 0; i < niter; i++) {
        if (i + 1 < niter) { loadStage((i + 1) & 1, (i + 1) << 5); CP_COMMIT(); CP_WAIT(1); }
        else               { CP_WAIT(0); }
        __syncthreads();
        compute(i & 1);
        __syncthreads();
    }

    // Epilogue
#pragma unroll
    for (int mt = 0; mt < 4; mt++) {
        int r0 = bm + wm * 64 + mt * 16 + qm;
#pragma unroll
        for (int nt = 0; nt < NT; nt++) {
            int c0 = bn + wn * (BN / 2) + nt * 8 + qk * 2;
            float v0 = acc[mt][nt][0], v1 = acc[mt][nt][1];
            float v2 = acc[mt][nt][2], v3 = acc[mt][nt][3];
            if (bias) {
                float b0 = (c0 < N) ? bias[c0] : 0.f;
                float b1 = (c0 + 1 < N) ? bias[c0 + 1] : 0.f;
                v0 += b0; v1 += b1; v2 += b0; v3 += b1;
            }
            if (EPI == 1) {
                v0 = 0.5f * v0 * (1.f + erff(v0 * 0.70710678118654752f));
                v1 = 0.5f * v1 * (1.f + erff(v1 * 0.70710678118654752f));
                v2 = 0.5f * v2 * (1.f + erff(v2 * 0.70710678118654752f));
                v3 = 0.5f * v3 * (1.f + erff(v3 * 0.70710678118654752f));
                __nv_bfloat162 h2, l2;
                split1(v0, h2.x, l2.x); split1(v1, h2.y, l2.y);
                *(__nv_bfloat162*)(Chi + (long)r0 * N + c0) = h2;
                *(__nv_bfloat162*)(Clo + (long)r0 * N + c0) = l2;
                split1(v2, h2.x, l2.x); split1(v3, h2.y, l2.y);
                *(__nv_bfloat162*)(Chi + (long)(r0 + 8) * N + c0) = h2;
                *(__nv_bfloat162*)(Clo + (long)(r0 + 8) * N + c0) = l2;
            } else {
                if (c0 < N) {
                    C[(long)r0 * N + c0] = v0;
                    C[(long)(r0 + 8) * N + c0] = v2;
                }
                if (c0 + 1 < N) {
                    C[(long)r0 * N + c0 + 1] = v1;
                    C[(long)(r0 + 8) * N + c0 + 1] = v3;
                }
            }
        }
    }
}

// ----------------------------------------------------------------------------
// FP32 scalar GEMM (exact path for sims -> top-k selection stability).
// ----------------------------------------------------------------------------
__global__ void __launch_bounds__(256) f32_gemm_kernel(
    const float* __restrict__ A, const float* __restrict__ B,
    float* __restrict__ C, int M, int N, int K,
    long sA, long sB, long sC)
{
    constexpr int BM = 128, BN = 128, BK = 8;
    int bz = blockIdx.z;
    A += bz * sA; B += bz * sB; C += bz * sC;
    int bm = blockIdx.y * BM, bn = blockIdx.x * BN;

    __shared__ float As[BK][BM + 4];
    __shared__ float Bs[BK][BN + 4];

    int tid = threadIdx.x;
    int tx = tid & 15, ty = tid >> 4;

    float acc[8][8];
#pragma unroll
    for (int i = 0; i < 8; i++)
#pragma unroll
        for (int j = 0; j < 8; j++) acc[i][j] = 0.f;

    for (int k0 = 0; k0 < K; k0 += BK) {
#pragma unroll
        for (int l = 0; l < 4; l++) {
            int lin = tid + l * 256;
            int kk = lin & 7, r = lin >> 3;
            int m = bm + r;
            As[kk][r] = (m < M) ? A[(long)m * K + k0 + kk] : 0.f;
        }
#pragma unroll
        for (int l = 0; l < 4; l++) {
            int lin = tid + l * 256;
            int kk = lin & 7, r = lin >> 3;
            int n = bn + r;
            Bs[kk][r] = (n < N) ? B[(long)n * K + k0 + kk] : 0.f;
        }
        __syncthreads();
#pragma unroll
        for (int k = 0; k < BK; k++) {
            float a[8], b[8];
            *(float4*)&a[0] = *(const float4*)&As[k][ty * 8];
            *(float4*)&a[4] = *(const float4*)&As[k][ty * 8 + 4];
            *(float4*)&b[0] = *(const float4*)&Bs[k][tx * 8];
            *(float4*)&b[4] = *(const float4*)&Bs[k][tx * 8 + 4];
#pragma unroll
            for (int i = 0; i < 8; i++)
#pragma unroll
                for (int j = 0; j < 8; j++)
                    acc[i][j] = fmaf(a[i], b[j], acc[i][j]);
        }
        __syncthreads();
    }
#pragma unroll
    for (int i = 0; i < 8; i++) {
        int m = bm + ty * 8 + i;
        if (m >= M) continue;
#pragma unroll
        for (int j = 0; j < 8; j++) {
            int n = bn + tx * 8 + j;
            if (n < N) C[(long)m * N + n] = acc[i][j];
        }
    }
}

// ----------------------------------------------------------------------------
// LayerNorm over last dim (D=768) + fused bf16 splits of x and x+qpos.
// ----------------------------------------------------------------------------
__global__ void __launch_bounds__(256) ln_kernel(
    const float* __restrict__ x, const float* __restrict__ add,
    const float* __restrict__ g, const float* __restrict__ b,
    const float* __restrict__ qpos,
    float* __restrict__ out,
    __nv_bfloat16* __restrict__ ohi, __nv_bfloat16* __restrict__ olo,
    __nv_bfloat16* __restrict__ oqhi, __nv_bfloat16* __restrict__ oqlo)
{
    int row = blockIdx.x, tid = threadIdx.x;
    const float* xr = x + (long)row * D;
    float vals[3];
    float s = 0.f, sq = 0.f;
#pragma unroll
    for (int i = 0; i < 3; i++) {
        int c = tid + i * 256;
        float v = xr[c];
        if (add) v += add[(long)row * D + c];
        vals[i] = v; s += v; sq += v * v;
    }
    __shared__ float rs[256], rq[256];
    rs[tid] = s; rq[tid] = sq;
    __syncthreads();
    for (int o = 128; o > 0; o >>= 1) {
        if (tid < o) { rs[tid] += rs[tid + o]; rq[tid] += rq[tid + o]; }
        __syncthreads();
    }
    float mu = rs[0] * (1.f / D);
    float var = rq[0] * (1.f / D) - mu * mu;
    float rstd = rsqrtf(var + EPS);
#pragma unroll
    for (int i = 0; i < 3; i++) {
        int c = tid + i * 256;
        long o = (long)row * D + c;
        float v = (vals[i] - mu) * rstd * g[c] + b[c];
        out[o] = v;
        __nv_bfloat16 h, l;
        split1(v, h, l);
        ohi[o] = h; olo[o] = l;
        split1(v + qpos[o], h, l);
        oqhi[o] = h; oqlo[o] = l;
    }
}

__global__ void __launch_bounds__(256) rownorm_kernel(
    const float* __restrict__ m, float* __restrict__ minv)
{
    int row = blockIdx.x, tid = threadIdx.x;
    float s = 0.f;
#pragma unroll
    for (int i = 0; i < 3; i++) {
        float v = m[(long)row * D + tid + i * 256];
        s += v * v;
    }
    __shared__ float rs[256];
    rs[tid] = s; __syncthreads();
    for (int o = 128; o > 0; o >>= 1) {
        if (tid < o) rs[tid] += rs[tid + o];
        __syncthreads();
    }
    if (tid == 0) minv[row] = rsqrtf(rs[0]);
}

// ----------------------------------------------------------------------------
// Top-32 per query row (iterative block argmax over smem copy).
// ----------------------------------------------------------------------------
__global__ void __launch_bounds__(256) topk_kernel(
    const float* __restrict__ sims, const float* __restrict__ minv,
    int* __restrict__ idx_out)
{
    int row = blockIdx.x;
    int b = row / NP;
    int tid = threadIdx.x;
    __shared__ float s[MNP];
    __shared__ float rmax[256];
    __shared__ int   rarg[256];
    for (int i = tid; i < MNP; i += 256)
        s[i] = sims[(long)row * MNP + i] * minv[b * MNP + i];
    __syncthreads();
    for (int t = 0; t < TOPK; t++) {
        float best = -INFINITY; int bi = 0x7fffffff;
        for (int i = tid; i < MNP; i += 256) {
            float v = s[i];
            if (v > best) { best = v; bi = i; }
        }
        rmax[tid] = best; rarg[tid] = bi;
        __syncthreads();
        for (int o = 128; o > 0; o >>= 1) {
            if (tid < o) {
                float ov = rmax[tid + o]; int oi = rarg[tid + o];
                if (ov > rmax[tid] || (ov == rmax[tid] && oi < rarg[tid])) {
                    rmax[tid] = ov; rarg[tid] = oi;
                }
            }
            __syncthreads();
        }
        if (tid == 0) {
            idx_out[row * TOPK + t] = rarg[0];
            s[rarg[0]] = -INFINITY;
        }
        __syncthreads();
    }
}

// ----------------------------------------------------------------------------
// Sparse cross-attention (32 gathered keys per query,head)
// ----------------------------------------------------------------------------
__global__ void __launch_bounds__(128) cross_attn_kernel(
    const float* __restrict__ q, const float* __restrict__ K,
    const float* __restrict__ V, const int* __restrict__ idx,
    float* __restrict__ out)
{
    int row = blockIdx.x;
    int b = row >> 7;
    int warp = threadIdx.x >> 5, lane = threadIdx.x & 31;
    int h = blockIdx.y * 4 + warp;

    __shared__ float qv[4][HD];
    __shared__ float ps[4][TOPK];
    __shared__ int   id[4][TOPK];

    const float* qr = q + (long)row * D + h * HD;
    qv[warp][lane] = qr[lane];
    qv[warp][lane + 32] = qr[lane + 32];
    int ix = idx[row * TOPK + lane];
    id[warp][lane] = ix;
    __syncwarp();

    const float* kr = K + ((long)(b * MNP + ix)) * D + h * HD;
    float s = 0.f;
#pragma unroll
    for (int d = 0; d < HD; d++) s = fmaf(qv[warp][d], kr[d], s);
    s *= 0.125f;

    float m = s;
#pragma unroll
    for (int o = 16; o > 0; o >>= 1) m = fmaxf(m, __shfl_xor_sync(0xffffffffu, m, o));
    float e = expf(s - m);
    float sum = e;
#pragma unroll
    for (int o = 16; o > 0; o >>= 1) sum += __shfl_xor_sync(0xffffffffu, sum, o);
    ps[warp][lane] = e / sum;
    __syncwarp();

    float acc0 = 0.f, acc1 = 0.f;
#pragma unroll
    for (int j = 0; j < TOPK; j++) {
        const float* vr = V + ((long)(b * MNP + id[warp][j])) * D + h * HD;
        float p = ps[warp][j];
        acc0 = fmaf(p, vr[lane], acc0);
        acc1 = fmaf(p, vr[lane + 32], acc1);
    }
    float* orow = out + (long)row * D + h * HD;
    orow[lane] = acc0;
    orow[lane + 32] = acc1;
}

// ----------------------------------------------------------------------------
// Dense self-attention over NP=128 keys -> writes bf16 hi/lo split directly.
// ----------------------------------------------------------------------------
__global__ void __launch_bounds__(128) self_attn_kernel(
    const float* __restrict__ qk, const float* __restrict__ v,
    __nv_bfloat16* __restrict__ ohi, __nv_bfloat16* __restrict__ olo)
{
    int row = blockIdx.x;
    int b = row >> 7;
    int h = blockIdx.y;
    int tid = threadIdx.x;

    __shared__ float qv[HD];
    __shared__ float sc[NP];
    __shared__ float red[128];

    const float* qr = qk + (long)row * (2 * D) + h * HD;
    if (tid < HD) qv[tid] = qr[tid];
    __syncthreads();

    const float* kr = qk + (long)(b * NP + tid) * (2 * D) + D + h * HD;
    float s = 0.f;
#pragma unroll
    for (int d = 0; d < HD; d++) s = fmaf(qv[d], kr[d], s);
    s *= 0.125f;

    red[tid] = s; __syncthreads();
    for (int o = 64; o > 0; o >>= 1) {
        if (tid < o) red[tid] = fmaxf(red[tid], red[tid + o]);
        __syncthreads();
    }
    float m = red[0]; __syncthreads();
    float e = expf(s - m);
    sc[tid] = e;
    red[tid] = e; __syncthreads();
    for (int o = 64; o > 0; o >>= 1) {
        if (tid < o) red[tid] += red[tid + o];
        __syncthreads();
    }
    float inv = 1.f / red[0];

    if (tid < HD) {
        float acc = 0.f;
        for (int j = 0; j < NP; j++)
            acc = fmaf(sc[j], v[(long)(b * NP + j) * D + h * HD + tid], acc);
        long o = (long)row * D + h * HD + tid;
        __nv_bfloat16 hh, ll;
        split1(acc * inv, hh, ll);
        ohi[o] = hh; olo[o] = ll;
    }
}

// ----------------------------------------------------------------------------
// BatchNorm stats -> fused scale/shift
// ----------------------------------------------------------------------------
__global__ void __launch_bounds__(256) bn_stats_kernel(
    const float* __restrict__ x, const float* __restrict__ g,
    const float* __restrict__ b, float* __restrict__ scale,
    float* __restrict__ shift)
{
    int f = blockIdx.x, tid = threadIdx.x;
    float s = 0.f, sq = 0.f;
    for (int r = tid; r < NTOK; r += 256) {
        float v = x[(long)r * D + f];
        s += v; sq += v * v;
    }
    __shared__ float rs[256], rq[256];
    rs[tid] = s; rq[tid] = sq;
    __syncthreads();
    for (int o = 128; o > 0; o >>= 1) {
        if (tid < o) { rs[tid] += rs[tid + o]; rq[tid] += rq[tid + o]; }
        __syncthreads();
    }
    if (tid == 0) {
        float mu = rs[0] * (1.f / NTOK);
        float var = rq[0] * (1.f / NTOK) - mu * mu;
        float rstd = rsqrtf(var + EPS);
        float sc = rstd * g[f];
        scale[f] = sc;
        shift[f] = b[f] - mu * sc;
    }
}

// ----------------------------------------------------------------------------
// Host orchestration
// ----------------------------------------------------------------------------
static void launch_hgemm(int bn_tile, int epi,
    const __nv_bfloat16* Ah, const __nv_bfloat16* Al,
    const __nv_bfloat16* Bh, const __nv_bfloat16* Bl,
    const float* bias, float* C, __nv_bfloat16* Chi, __nv_bfloat16* Clo,
    int M, int N, int K)
{
    if (bn_tile == 128) {
        dim3 grid((N + 127) / 128, M / 128);
        int smem = 2 * 2 * 256 * 80;
        if (epi == 0) {
            cudaFuncSetAttribute(hgemm_kernel<128,0>, cudaFuncAttributeMaxDynamicSharedMemorySize, smem);
            hgemm_kernel<128,0><<<grid, 128, smem>>>(Ah, Al, Bh, Bl, bias, C, Chi, Clo, M, N, K);
        } else {
            cudaFuncSetAttribute(hgemm_kernel<128,1>, cudaFuncAttributeMaxDynamicSharedMemorySize, smem);
            hgemm_kernel<128,1><<<grid, 128, smem>>>(Ah, Al, Bh, Bl, bias, C, Chi, Clo, M, N, K);
        }
    } else {
        dim3 grid((N + 63) / 64, M / 128);
        int smem = 2 * 2 * 192 * 80;
        cudaFuncSetAttribute(hgemm_kernel<64,0>, cudaFuncAttributeMaxDynamicSharedMemorySize, smem);
        hgemm_kernel<64,0><<<grid, 128, smem>>>(Ah, Al, Bh, Bl, bias, C, Chi, Clo, M, N, K);
    }
}

extern "C" void kernel_launch(void* const* d_in, const int* in_sizes, int n_in,
                              void* d_out, int out_size)
{
    const float* tgt      = (const float*)d_in[0];
    const float* memory   = (const float*)d_in[1];
    const float* qpos     = (const float*)d_in[2];
    const float* kpos     = (const float*)d_in[3];
    const float* norm0_g  = (const float*)d_in[4];
    const float* norm0_b  = (const float*)d_in[5];
    const float* l1_w     = (const float*)d_in[6];
    const float* l1_b     = (const float*)d_in[7];
    const float* l2_w     = (const float*)d_in[8];
    const float* l2_b     = (const float*)d_in[9];
    const float* l3_w     = (const float*)d_in[10];
    const float* l3_b     = (const float*)d_in[11];
    const float* n1_g     = (const float*)d_in[12];
    const float* n1_b     = (const float*)d_in[13];
    const float* n2_g     = (const float*)d_in[14];
    const float* n2_b     = (const float*)d_in[15];
    const float* n3_g     = (const float*)d_in[16];
    const float* n3_b     = (const float*)d_in[17];
    const float* sa_in_w  = (const float*)d_in[18];
    const float* sa_in_b  = (const float*)d_in[19];
    const float* sa_out_w = (const float*)d_in[20];
    const float* sa_out_b = (const float*)d_in[21];
    const float* ff1_w    = (const float*)d_in[22];
    const float* ff1_b    = (const float*)d_in[23];
    const float* ff2_w    = (const float*)d_in[24];
    const float* ff2_b    = (const float*)d_in[25];
    const float* bn_g     = (const float*)d_in[26];
    const float* bn_b     = (const float*)d_in[27];
    const float* cls_w    = (const float*)d_in[28];

    float *x, *tmp, *q, *qk, *v, *attn, *Kb, *Vb, *sims, *minv, *bnsc, *bnsh;
    int* idx;
    __nv_bfloat16 *whi, *wlo, *mkhi, *mklo, *mhi, *mlo;
    __nv_bfloat16 *xhi, *xlo, *xqhi, *xqlo, *h1hi, *h1lo, *sahi, *salo, *cihi, *cilo;
    cudaGetSymbolAddress((void**)&x,    g_x);
    cudaGetSymbolAddress((void**)&tmp,  g_tmp);
    cudaGetSymbolAddress((void**)&q,    g_q);
    cudaGetSymbolAddress((void**)&qk,   g_qk);
    cudaGetSymbolAddress((void**)&v,    g_v);
    cudaGetSymbolAddress((void**)&attn, g_attn);
    cudaGetSymbolAddress((void**)&Kb,   g_K);
    cudaGetSymbolAddress((void**)&Vb,   g_V);
    cudaGetSymbolAddress((void**)&sims, g_sims);
    cudaGetSymbolAddress((void**)&idx,  g_idx);
    cudaGetSymbolAddress((void**)&minv, g_minv);
    cudaGetSymbolAddress((void**)&bnsc, g_bnscale);
    cudaGetSymbolAddress((void**)&bnsh, g_bnshift);
    cudaGetSymbolAddress((void**)&whi,  g_whi);
    cudaGetSymbolAddress((void**)&wlo,  g_wlo);
    cudaGetSymbolAddress((void**)&mkhi, g_mkhi);
    cudaGetSymbolAddress((void**)&mklo, g_mklo);
    cudaGetSymbolAddress((void**)&mhi,  g_mhi);
    cudaGetSymbolAddress((void**)&mlo,  g_mlo);
    cudaGetSymbolAddress((void**)&xhi,  g_xhi);
    cudaGetSymbolAddress((void**)&xlo,  g_xlo);
    cudaGetSymbolAddress((void**)&xqhi, g_xqhi);
    cudaGetSymbolAddress((void**)&xqlo, g_xqlo);
    cudaGetSymbolAddress((void**)&h1hi, g_h1hi);
    cudaGetSymbolAddress((void**)&h1lo, g_h1lo);
    cudaGetSymbolAddress((void**)&sahi, g_sahi);
    cudaGetSymbolAddress((void**)&salo, g_salo);
    cudaGetSymbolAddress((void**)&cihi, g_cihi);
    cudaGetSymbolAddress((void**)&cilo, g_cilo);

    // ---- one-time (per call) splits ----
    split_kernel<<<4096, 256>>>(l1_w,     whi + OFF_L1,    wlo + OFF_L1,    (long)NLAYERS*D*D);
    split_kernel<<<4096, 256>>>(l2_w,     whi + OFF_L2,    wlo + OFF_L2,    (long)NLAYERS*D*D);
    split_kernel<<<4096, 256>>>(l3_w,     whi + OFF_L3,    wlo + OFF_L3,    (long)NLAYERS*D*D);
    split_kernel<<<4096, 256>>>(sa_in_w,  whi + OFF_SAIN,  wlo + OFF_SAIN,  (long)NLAYERS*3*D*D);
    split_kernel<<<4096, 256>>>(sa_out_w, whi + OFF_SAOUT, wlo + OFF_SAOUT, (long)NLAYERS*D*D);
    split_kernel<<<4096, 256>>>(ff1_w,    whi + OFF_FF1,   wlo + OFF_FF1,   (long)NLAYERS*DFF*D);
    split_kernel<<<4096, 256>>>(ff2_w,    whi + OFF_FF2,   wlo + OFF_FF2,   (long)NLAYERS*D*DFF);
    split_kernel<<<4096, 256>>>(cls_w,    whi + OFF_CLS,   wlo + OFF_CLS,   (long)NC*D);
    split_add_kernel<<<8192, 256>>>(memory, kpos, mkhi, mklo, (long)NMEM*D);
    split_kernel<<<8192, 256>>>(memory, mhi, mlo, (long)NMEM*D);

    rownorm_kernel<<<NMEM, 256>>>(memory, minv);
    ln_kernel<<<NTOK, 256>>>(tgt, nullptr, norm0_g, norm0_b, qpos,
                             x, xhi, xlo, xqhi, xqlo);

    for (int l = 0; l < NLAYERS; l++) {
        long wdd = (long)l * D * D;
        const __nv_bfloat16* l1h = whi + OFF_L1 + wdd;  const __nv_bfloat16* l1l = wlo + OFF_L1 + wdd;
        const __nv_bfloat16* l2h = whi + OFF_L2 + wdd;  const __nv_bfloat16* l2l = wlo + OFF_L2 + wdd;
        const __nv_bfloat16* l3h = whi + OFF_L3 + wdd;  const __nv_bfloat16* l3l = wlo + OFF_L3 + wdd;
        const __nv_bfloat16* sih = whi + OFF_SAIN + (long)l*3*D*D;
        const __nv_bfloat16* sil = wlo + OFF_SAIN + (long)l*3*D*D;
        const __nv_bfloat16* soh = whi + OFF_SAOUT + wdd;
        const __nv_bfloat16* sol = wlo + OFF_SAOUT + wdd;
        const __nv_bfloat16* f1h = whi + OFF_FF1 + (long)l*DFF*D;
        const __nv_bfloat16* f1l = wlo + OFF_FF1 + (long)l*DFF*D;
        const __nv_bfloat16* f2h = whi + OFF_FF2 + (long)l*D*DFF;
        const __nv_bfloat16* f2l = wlo + OFF_FF2 + (long)l*D*DFF;
        const float* l1bb = l1_b + (long)l * D;
        const float* l2bb = l2_b + (long)l * D;
        const float* l3bb = l3_b + (long)l * D;
        const float* sab  = sa_in_b + (long)l * 3 * D;
        const float* sob  = sa_out_b + (long)l * D;
        const float* f1b  = ff1_b + (long)l * DFF;
        const float* f2b  = ff2_b + (long)l * D;

        // sims[b] = x[b] @ memory[b]^T  — FP32 EXACT (top-k selection stability)
        f32_gemm_kernel<<<dim3(MNP / 128, 1, BS), 256>>>(
            x, memory, sims, NP, MNP, D,
            (long)NP * D, (long)MNP * D, (long)NP * MNP);

        topk_kernel<<<NTOK, 256>>>(sims, minv, idx);

        // q = (x + qpos) @ l1_w^T + b
        launch_hgemm(64, 0, xqhi, xqlo, l1h, l1l, l1bb, q, nullptr, nullptr, NTOK, D, D);

        // K = (mem + kpos) @ l2_w^T + b ; V = mem @ l3_w^T + b
        launch_hgemm(128, 0, mkhi, mklo, l2h, l2l, l2bb, Kb, nullptr, nullptr, NMEM, D, D);
        launch_hgemm(128, 0, mhi,  mlo,  l3h, l3l, l3bb, Vb, nullptr, nullptr, NMEM, D, D);

        cross_attn_kernel<<<dim3(NTOK, NH / 4), 128>>>(q, Kb, Vb, idx, attn);

        ln_kernel<<<NTOK, 256>>>(x, attn, n1_g + (long)l * D, n1_b + (long)l * D,
                                 qpos, x, xhi, xlo, xqhi, xqlo);

        // self-attn projections: [q;k] from x+qpos ; v from x
        launch_hgemm(128, 0, xqhi, xqlo, sih, sil, sab, qk, nullptr, nullptr, NTOK, 2 * D, D);
        launch_hgemm(64, 0, xhi, xlo, sih + (long)2*D*D, sil + (long)2*D*D, sab + 2*D,
                     v, nullptr, nullptr, NTOK, D, D);

        self_attn_kernel<<<dim3(NTOK, NH), 128>>>(qk, v, sahi, salo);

        launch_hgemm(64, 0, sahi, salo, soh, sol, sob, tmp, nullptr, nullptr, NTOK, D, D);

        ln_kernel<<<NTOK, 256>>>(x, tmp, n2_g + (long)l * D, n2_b + (long)l * D,
                                 qpos, x, xhi, xlo, xqhi, xqlo);

        // FFN: h1 = gelu(x@ff1^T + b1) -> bf16 split ; tmp = h1@ff2^T + b2
        {
            dim3 grid(DFF / 128, NTOK / 128);
            int smem = 2 * 2 * 256 * 80;
            cudaFuncSetAttribute(hgemm_kernel<128,1>, cudaFuncAttributeMaxDynamicSharedMemorySize, smem);
            hgemm_kernel<128,1><<<grid, 128, smem>>>(xhi, xlo, f1h, f1l, f1b,
                                                     nullptr, h1hi, h1lo, NTOK, DFF, D);
        }
        launch_hgemm(64, 0, h1hi, h1lo, f2h, f2l, f2b, tmp, nullptr, nullptr, NTOK, D, DFF);

        ln_kernel<<<NTOK, 256>>>(x, tmp, n3_g + (long)l * D, n3_b + (long)l * D,
                                 qpos, x, xhi, xlo, xqhi, xqlo);
    }

    bn_stats_kernel<<<D, 256>>>(x, bn_g, bn_b, bnsc, bnsh);
    split_affine_kernel<<<2048, 256>>>(x, bnsc, bnsh, cihi, cilo, (long)NTOK * D);

    float* out = (float*)d_out;
    long xsz = (long)NTOK * D;
    long csz = (long)NTOK * NC;

    if ((long)out_size >= xsz + csz) {
        cudaMemcpyAsync(out, x, sizeof(float) * xsz, cudaMemcpyDeviceToDevice, 0);
        launch_hgemm(64, 0, cihi, cilo, whi + OFF_CLS, wlo + OFF_CLS, nullptr,
                     out + xsz, nullptr, nullptr, NTOK, NC, D);
    } else if ((long)out_size == csz) {
        launch_hgemm(64, 0, cihi, cilo, whi + OFF_CLS, wlo + OFF_CLS, nullptr,
                     out, nullptr, nullptr, NTOK, NC, D);
    } else {
        cudaMemcpyAsync(out, x, sizeof(float) * ((long)out_size < xsz ? out_size : xsz),
                        cudaMemcpyDeviceToDevice, 0);
    }
}